// round 1
// baseline (speedup 1.0000x reference)
#include <cuda_runtime.h>
#include <math.h>

// Problem constants
#define Bc   4
#define Lc   16384
#define Dc   128
#define DIc  256
#define DSc  16
#define DTRc 8
#define Kc   4
#define Nc   (Bc*Lc)          // 65536 tokens
#define NCH  128              // chunks per sequence
#define Tc   (Lc/NCH)         // 128 steps per chunk
#define EPSc 1e-5f

// ---------------- scratch (device globals; no allocations) ----------------
__device__ float g_xi [Nc*DIc];     // conv input  (permuted order)
__device__ float g_z  [Nc*DIc];     // gate
__device__ float g_xc [Nc*DIc];     // conv+silu output
__device__ float g_dt [Nc*DIc];     // softplus(dt)
__device__ float g_dbc[Nc*40];      // [dt8 | B | C]
__device__ float g_ch [Bc*NCH*DIc*DSc]; // per-chunk local final states
__device__ float g_sdt[Bc*NCH*DIc];     // per-chunk sum of dt
__device__ float g_hin[Bc*NCH*DIc*DSc]; // per-chunk carry-in states
__device__ float g_y  [Nc*DIc];     // gated scan output
__device__ float g_op [Nc*Dc];      // out_proj result (permuted order)

// =====================================================================
// K1: fused embed + gather(perm) + RMSNorm + in_proj GEMM (M=65536,K=128,N=512)
// =====================================================================
__global__ __launch_bounds__(256) void k_fused_in(
    const float* __restrict__ feats, const int* __restrict__ coords,
    const float* __restrict__ pos_w, const float* __restrict__ pos_b,
    const float* __restrict__ rms_w, const float* __restrict__ W,
    const int* __restrict__ perm)
{
    __shared__ float As[64][128];   // normalized input rows (full K)
    __shared__ float Bs[64][64];    // weight tile
    const int tid  = threadIdx.x;
    const int lane = tid & 31, wrp = tid >> 5;
    const int m0 = blockIdx.x * 64;
    const int n0 = blockIdx.y * 64;

    // --- load + embed + normalize 64 rows (one warp per row, 8 rows/warp) ---
    for (int r = wrp; r < 64; r += 8) {
        int m   = m0 + r;                         // permuted token index b*L+t
        int src = (m & ~(Lc-1)) + perm[m];        // original row b*L + perm[b][t]
        float c0 = (float)coords[src*3+0];
        float c1 = (float)coords[src*3+1];
        float c2 = (float)coords[src*3+2];
        float4 f4 = *(const float4*)(feats + (size_t)src*Dc + lane*4);
        float v[4]; float ss = 0.f;
        #pragma unroll
        for (int j = 0; j < 4; ++j) {
            int c = lane*4 + j;
            float val = (&f4.x)[j] + c0*pos_w[c] + c1*pos_w[Dc+c]
                        + c2*pos_w[2*Dc+c] + pos_b[c];
            v[j] = val; ss += val*val;
        }
        #pragma unroll
        for (int o = 16; o > 0; o >>= 1) ss += __shfl_xor_sync(0xffffffffu, ss, o);
        float rs = rsqrtf(ss * (1.f/Dc) + EPSc);
        #pragma unroll
        for (int j = 0; j < 4; ++j) {
            int c = lane*4 + j;
            As[r][c] = v[j] * rs * rms_w[c];
        }
    }
    __syncthreads();

    // --- 64x64 tile GEMM, 4x4 micro-tile per thread ---
    float acc[4][4] = {};
    const int ty = tid >> 4, tx = tid & 15;
    const int r0 = ty*4, cc0 = tx*4;
    for (int kk = 0; kk < 2; ++kk) {
        for (int i = tid; i < 64*64; i += 256) {
            int r = i >> 6, c = i & 63;
            Bs[r][c] = W[(size_t)(kk*64 + r)*512 + n0 + c];
        }
        __syncthreads();
        #pragma unroll 16
        for (int k = 0; k < 64; ++k) {
            float a0 = As[r0+0][kk*64+k];
            float a1 = As[r0+1][kk*64+k];
            float a2 = As[r0+2][kk*64+k];
            float a3 = As[r0+3][kk*64+k];
            float4 b4 = *(const float4*)&Bs[k][cc0];
            acc[0][0] += a0*b4.x; acc[0][1] += a0*b4.y; acc[0][2] += a0*b4.z; acc[0][3] += a0*b4.w;
            acc[1][0] += a1*b4.x; acc[1][1] += a1*b4.y; acc[1][2] += a1*b4.z; acc[1][3] += a1*b4.w;
            acc[2][0] += a2*b4.x; acc[2][1] += a2*b4.y; acc[2][2] += a2*b4.z; acc[2][3] += a2*b4.w;
            acc[3][0] += a3*b4.x; acc[3][1] += a3*b4.y; acc[3][2] += a3*b4.z; acc[3][3] += a3*b4.w;
        }
        __syncthreads();
    }
    #pragma unroll
    for (int i = 0; i < 4; ++i) {
        int m = m0 + r0 + i;
        #pragma unroll
        for (int j = 0; j < 4; ++j) {
            int n = n0 + cc0 + j;
            if (n < DIc) g_xi[(size_t)m*DIc + n]        = acc[i][j];
            else         g_z [(size_t)m*DIc + (n-DIc)]  = acc[i][j];
        }
    }
}

// =====================================================================
// K2: depthwise causal conv (K=4) + silu
// =====================================================================
__global__ __launch_bounds__(256) void k_conv(
    const float* __restrict__ cw, const float* __restrict__ cb)
{
    int idx = blockIdx.x*256 + threadIdx.x;   // over Nc*DIc
    int d = idx & (DIc-1);
    int t = (idx >> 8) & (Lc-1);
    float acc = cb[d];
    #pragma unroll
    for (int j = 0; j < Kc; ++j) {
        int tt = t - (Kc-1) + j;
        if (tt >= 0) acc += g_xi[idx + (j-(Kc-1))*DIc] * cw[d*Kc + j];
    }
    g_xc[idx] = acc / (1.f + __expf(-acc));
}

// =====================================================================
// K3: dbc = xc @ x_proj_w  (M=65536, K=256, N=40 padded to 64)
// =====================================================================
__global__ __launch_bounds__(256) void k_xproj(const float* __restrict__ Wg)
{
    __shared__ float As[64][64];
    __shared__ float Bs[64][64];
    int tid = threadIdx.x;
    int m0 = blockIdx.x*64;
    float acc[4][4] = {};
    int ty = tid >> 4, tx = tid & 15;
    int r0 = ty*4, c0 = tx*4;
    for (int kk = 0; kk < 256; kk += 64) {
        for (int i = tid; i < 4096; i += 256) {
            int r = i >> 6, c = i & 63;
            As[r][c] = g_xc[(size_t)(m0+r)*DIc + kk + c];
            Bs[r][c] = (c < 40) ? Wg[(size_t)(kk+r)*40 + c] : 0.f;
        }
        __syncthreads();
        #pragma unroll 16
        for (int k = 0; k < 64; ++k) {
            float a0 = As[r0+0][k], a1 = As[r0+1][k], a2 = As[r0+2][k], a3 = As[r0+3][k];
            float4 b4 = *(const float4*)&Bs[k][c0];
            acc[0][0] += a0*b4.x; acc[0][1] += a0*b4.y; acc[0][2] += a0*b4.z; acc[0][3] += a0*b4.w;
            acc[1][0] += a1*b4.x; acc[1][1] += a1*b4.y; acc[1][2] += a1*b4.z; acc[1][3] += a1*b4.w;
            acc[2][0] += a2*b4.x; acc[2][1] += a2*b4.y; acc[2][2] += a2*b4.z; acc[2][3] += a2*b4.w;
            acc[3][0] += a3*b4.x; acc[3][1] += a3*b4.y; acc[3][2] += a3*b4.z; acc[3][3] += a3*b4.w;
        }
        __syncthreads();
    }
    #pragma unroll
    for (int i = 0; i < 4; ++i) {
        int m = m0 + r0 + i;
        #pragma unroll
        for (int j = 0; j < 4; ++j) {
            int n = c0 + j;
            if (n < 40) g_dbc[(size_t)m*40 + n] = acc[i][j];
        }
    }
}

// =====================================================================
// K4: dt = softplus(dt8 @ dt_proj_w + dt_proj_b)   (low-rank path, K=8)
// =====================================================================
__global__ __launch_bounds__(256) void k_dt(
    const float* __restrict__ dtw, const float* __restrict__ dtb)
{
    int m = blockIdx.x;
    __shared__ float dr[8];
    int tid = threadIdx.x;
    if (tid < 8) dr[tid] = g_dbc[(size_t)m*40 + tid];
    __syncthreads();
    float v = dtb[tid];
    #pragma unroll
    for (int k = 0; k < 8; ++k) v += dr[k]*dtw[k*DIc + tid];
    float sp = (v > 20.f) ? v : log1pf(__expf(v));
    g_dt[(size_t)m*DIc + tid] = sp;
}

// =====================================================================
// K5: scan pass 1 — per-chunk local final state (from zero) + sum(dt)
//     exp(dt*A_s) = exp(dt*A_0)^(s+1) when A_s = (s+1)*A_0 (checked at runtime)
// =====================================================================
__global__ __launch_bounds__(256) void k_scan1(const float* __restrict__ A_log)
{
    __shared__ float Bsh[Tc][DSc];
    int blk = blockIdx.x;                // b*NCH + ch
    int b = blk >> 7, ch = blk & (NCH-1);
    int base = b*Lc + ch*Tc;
    int tid = threadIdx.x;
    for (int i = tid; i < Tc*DSc; i += 256) {
        int t = i >> 4, s = i & 15;
        Bsh[t][s] = g_dbc[(size_t)(base+t)*40 + DTRc + s];
    }
    __syncthreads();
    int d = tid;
    float a0 = -__expf(A_log[d*DSc]);
    bool uni = true;
    #pragma unroll
    for (int s = 1; s < DSc; ++s) {
        float as = -__expf(A_log[d*DSc+s]);
        uni = uni && (fabsf(as - (float)(s+1)*a0) <= 1e-4f*fabsf((float)(s+1)*a0) + 1e-6f);
    }
    float h[DSc];
    #pragma unroll
    for (int s = 0; s < DSc; ++s) h[s] = 0.f;
    float sdt = 0.f;
    if (uni) {
        for (int t = 0; t < Tc; ++t) {
            float dt = g_dt[(size_t)(base+t)*DIc + d];
            float x  = g_xc[(size_t)(base+t)*DIc + d];
            sdt += dt;
            float u = dt*x;
            float e1 = __expf(dt*a0);
            float pk = 1.f;
            #pragma unroll
            for (int s = 0; s < DSc; ++s) { pk *= e1; h[s] = pk*h[s] + u*Bsh[t][s]; }
        }
    } else {
        for (int t = 0; t < Tc; ++t) {
            float dt = g_dt[(size_t)(base+t)*DIc + d];
            float x  = g_xc[(size_t)(base+t)*DIc + d];
            sdt += dt;
            float u = dt*x;
            #pragma unroll
            for (int s = 0; s < DSc; ++s) {
                float as = -__expf(A_log[d*DSc+s]);
                h[s] = __expf(dt*as)*h[s] + u*Bsh[t][s];
            }
        }
    }
    size_t co = ((size_t)blk*DIc + d)*DSc;
    #pragma unroll
    for (int s = 0; s < DSc; ++s) g_ch[co+s] = h[s];
    g_sdt[(size_t)blk*DIc + d] = sdt;
}

// =====================================================================
// K6: sequential chunk combine -> carry-in state per chunk
// =====================================================================
__global__ __launch_bounds__(256) void k_comb(const float* __restrict__ A_log)
{
    int id = blockIdx.x*256 + threadIdx.x;   // < Bc*DIc*DSc = 16384
    int b = id >> 12;
    int d = (id >> 4) & (DIc-1);
    int s = id & 15;
    float a = -__expf(A_log[d*DSc + s]);
    float H = 0.f;
    for (int ch = 0; ch < NCH; ++ch) {
        size_t off = ((size_t)(b*NCH+ch)*DIc + d)*DSc + s;
        g_hin[off] = H;
        float sdt = g_sdt[(size_t)(b*NCH+ch)*DIc + d];
        H = __expf(a*sdt)*H + g_ch[off];
    }
}

// =====================================================================
// K7: scan pass 2 — exact replay with carry-in, fused +xc*D and *silu(z)
// =====================================================================
__global__ __launch_bounds__(256) void k_scan2(
    const float* __restrict__ A_log, const float* __restrict__ Dp)
{
    __shared__ float Bsh[Tc][DSc];
    __shared__ float Csh[Tc][DSc];
    int blk = blockIdx.x;
    int b = blk >> 7, ch = blk & (NCH-1);
    int base = b*Lc + ch*Tc;
    int tid = threadIdx.x;
    for (int i = tid; i < Tc*DSc; i += 256) {
        int t = i >> 4, s = i & 15;
        Bsh[t][s] = g_dbc[(size_t)(base+t)*40 + DTRc + s];
        Csh[t][s] = g_dbc[(size_t)(base+t)*40 + DTRc + DSc + s];
    }
    __syncthreads();
    int d = tid;
    float a0 = -__expf(A_log[d*DSc]);
    bool uni = true;
    #pragma unroll
    for (int s = 1; s < DSc; ++s) {
        float as = -__expf(A_log[d*DSc+s]);
        uni = uni && (fabsf(as - (float)(s+1)*a0) <= 1e-4f*fabsf((float)(s+1)*a0) + 1e-6f);
    }
    float h[DSc];
    size_t ho = ((size_t)blk*DIc + d)*DSc;
    #pragma unroll
    for (int s = 0; s < DSc; ++s) h[s] = g_hin[ho+s];
    float dp = Dp[d];
    if (uni) {
        for (int t = 0; t < Tc; ++t) {
            float dt = g_dt[(size_t)(base+t)*DIc + d];
            float x  = g_xc[(size_t)(base+t)*DIc + d];
            float u = dt*x;
            float e1 = __expf(dt*a0);
            float pk = 1.f, y = 0.f;
            #pragma unroll
            for (int s = 0; s < DSc; ++s) {
                pk *= e1;
                h[s] = pk*h[s] + u*Bsh[t][s];
                y += h[s]*Csh[t][s];
            }
            float zz = g_z[(size_t)(base+t)*DIc + d];
            float sil = zz / (1.f + __expf(-zz));
            g_y[(size_t)(base+t)*DIc + d] = (y + x*dp)*sil;
        }
    } else {
        for (int t = 0; t < Tc; ++t) {
            float dt = g_dt[(size_t)(base+t)*DIc + d];
            float x  = g_xc[(size_t)(base+t)*DIc + d];
            float u = dt*x;
            float y = 0.f;
            #pragma unroll
            for (int s = 0; s < DSc; ++s) {
                float as = -__expf(A_log[d*DSc+s]);
                h[s] = __expf(dt*as)*h[s] + u*Bsh[t][s];
                y += h[s]*Csh[t][s];
            }
            float zz = g_z[(size_t)(base+t)*DIc + d];
            float sil = zz / (1.f + __expf(-zz));
            g_y[(size_t)(base+t)*DIc + d] = (y + x*dp)*sil;
        }
    }
}

// =====================================================================
// K8: out = y @ out_proj_w  (M=65536, K=256, N=128)
// =====================================================================
__global__ __launch_bounds__(256) void k_outproj(const float* __restrict__ Wg)
{
    __shared__ float As[64][64];
    __shared__ float Bs[64][64];
    int tid = threadIdx.x;
    int m0 = blockIdx.x*64;
    int n0 = blockIdx.y*64;
    float acc[4][4] = {};
    int ty = tid >> 4, tx = tid & 15;
    int r0 = ty*4, c0 = tx*4;
    for (int kk = 0; kk < 256; kk += 64) {
        for (int i = tid; i < 4096; i += 256) {
            int r = i >> 6, c = i & 63;
            As[r][c] = g_y[(size_t)(m0+r)*DIc + kk + c];
            Bs[r][c] = Wg[(size_t)(kk+r)*Dc + n0 + c];
        }
        __syncthreads();
        #pragma unroll 16
        for (int k = 0; k < 64; ++k) {
            float a0 = As[r0+0][k], a1 = As[r0+1][k], a2 = As[r0+2][k], a3 = As[r0+3][k];
            float4 b4 = *(const float4*)&Bs[k][c0];
            acc[0][0] += a0*b4.x; acc[0][1] += a0*b4.y; acc[0][2] += a0*b4.z; acc[0][3] += a0*b4.w;
            acc[1][0] += a1*b4.x; acc[1][1] += a1*b4.y; acc[1][2] += a1*b4.z; acc[1][3] += a1*b4.w;
            acc[2][0] += a2*b4.x; acc[2][1] += a2*b4.y; acc[2][2] += a2*b4.z; acc[2][3] += a2*b4.w;
            acc[3][0] += a3*b4.x; acc[3][1] += a3*b4.y; acc[3][2] += a3*b4.z; acc[3][3] += a3*b4.w;
        }
        __syncthreads();
    }
    #pragma unroll
    for (int i = 0; i < 4; ++i) {
        int m = m0 + r0 + i;
        #pragma unroll
        for (int j = 0; j < 4; ++j) {
            g_op[(size_t)m*Dc + n0 + c0 + j] = acc[i][j];
        }
    }
}

// =====================================================================
// K9: LayerNorm + inverse-permutation scatter (one warp per row)
// =====================================================================
__global__ __launch_bounds__(256) void k_ln(
    const int* __restrict__ perm,
    const float* __restrict__ ln_w, const float* __restrict__ ln_b,
    float* __restrict__ out)
{
    int wrp = threadIdx.x >> 5, lane = threadIdx.x & 31;
    int m = blockIdx.x*8 + wrp;                 // permuted row
    float4 v4 = *(const float4*)(g_op + (size_t)m*Dc + lane*4);
    float v[4] = {v4.x, v4.y, v4.z, v4.w};
    float sum = 0.f, ss = 0.f;
    #pragma unroll
    for (int j = 0; j < 4; ++j) { sum += v[j]; ss += v[j]*v[j]; }
    #pragma unroll
    for (int o = 16; o > 0; o >>= 1) {
        sum += __shfl_xor_sync(0xffffffffu, sum, o);
        ss  += __shfl_xor_sync(0xffffffffu, ss, o);
    }
    float mu  = sum * (1.f/Dc);
    float var = ss * (1.f/Dc) - mu*mu;
    float rs  = rsqrtf(var + EPSc);
    int dst = (m & ~(Lc-1)) + perm[m];          // b*L + perm[b][t]
    float4 o4;
    int c = lane*4;
    o4.x = (v[0]-mu)*rs*ln_w[c+0] + ln_b[c+0];
    o4.y = (v[1]-mu)*rs*ln_w[c+1] + ln_b[c+1];
    o4.z = (v[2]-mu)*rs*ln_w[c+2] + ln_b[c+2];
    o4.w = (v[3]-mu)*rs*ln_w[c+3] + ln_b[c+3];
    *(float4*)(out + (size_t)dst*Dc + c) = o4;
}

// =====================================================================
extern "C" void kernel_launch(void* const* d_in, const int* in_sizes, int n_in,
                              void* d_out, int out_size)
{
    const float* feats      = (const float*)d_in[0];
    const float* pos_w      = (const float*)d_in[1];
    const float* pos_b      = (const float*)d_in[2];
    const float* rms_w      = (const float*)d_in[3];
    const float* in_proj_w  = (const float*)d_in[4];
    const float* conv_w     = (const float*)d_in[5];
    const float* conv_b     = (const float*)d_in[6];
    const float* x_proj_w   = (const float*)d_in[7];
    const float* dt_proj_w  = (const float*)d_in[8];
    const float* dt_proj_b  = (const float*)d_in[9];
    const float* A_log      = (const float*)d_in[10];
    const float* D_param    = (const float*)d_in[11];
    const float* out_proj_w = (const float*)d_in[12];
    const float* ln_w       = (const float*)d_in[13];
    const float* ln_b       = (const float*)d_in[14];
    const int*   coords     = (const int*)  d_in[15];
    const int*   perm       = (const int*)  d_in[16];
    float* out = (float*)d_out;

    k_fused_in<<<dim3(Nc/64, 512/64), 256>>>(feats, coords, pos_w, pos_b,
                                             rms_w, in_proj_w, perm);
    k_conv   <<<(Nc*DIc)/256, 256>>>(conv_w, conv_b);
    k_xproj  <<<dim3(Nc/64, 1), 256>>>(x_proj_w);
    k_dt     <<<Nc, 256>>>(dt_proj_w, dt_proj_b);
    k_scan1  <<<Bc*NCH, 256>>>(A_log);
    k_comb   <<<(Bc*DIc*DSc)/256, 256>>>(A_log);
    k_scan2  <<<Bc*NCH, 256>>>(A_log, D_param);
    k_outproj<<<dim3(Nc/64, Dc/64), 256>>>(out_proj_w);
    k_ln     <<<Nc/8, 256>>>(perm, ln_w, ln_b, out);
}

// round 2
// speedup vs baseline: 1.1188x; 1.1188x over previous
#include <cuda_runtime.h>
#include <math.h>

// Problem constants
#define Bc   4
#define Lc   16384
#define Dc   128
#define DIc  256
#define DSc  16
#define DTRc 8
#define Kc   4
#define Nc   (Bc*Lc)          // 65536 tokens
#define NCH  128              // chunks per sequence
#define Tc   (Lc/NCH)         // 128 steps per chunk
#define EPSc 1e-5f

// ---------------- scratch (device globals; no allocations) ----------------
__device__ float g_xi [Nc*DIc];     // conv input  (permuted order)
__device__ float g_z  [Nc*DIc];     // gate
__device__ float g_xc [Nc*DIc];     // conv+silu output
__device__ float g_dt [Nc*DIc];     // softplus(dt)
__device__ float g_dbc[Nc*40];      // [dt8 | B | C]
__device__ float g_ch [Bc*NCH*DIc*DSc]; // per-chunk local final states
__device__ float g_sdt[Bc*NCH*DIc];     // per-chunk sum of dt
__device__ float g_hin[Bc*NCH*DIc*DSc]; // per-chunk carry-in states
__device__ float g_y  [Nc*DIc];     // gated scan output
__device__ float g_op [Nc*Dc];      // out_proj result (permuted order)

// ---------------- f32x2 helpers (sm_100+) ----------------
typedef unsigned long long u64;
__device__ __forceinline__ u64 pk2(float x, float y) {
    u64 r;
    asm("mov.b64 %0, {%1, %2};" : "=l"(r)
        : "r"(__float_as_uint(x)), "r"(__float_as_uint(y)));
    return r;
}
__device__ __forceinline__ void fma2(u64 &d, u64 a, u64 b) {
    asm("fma.rn.f32x2 %0, %1, %2, %3;" : "=l"(d) : "l"(a), "l"(b), "l"(d));
}
__device__ __forceinline__ void upk2(u64 v, float &lo, float &hi) {
    unsigned int l, h;
    asm("mov.b64 {%0, %1}, %2;" : "=r"(l), "=r"(h) : "l"(v));
    lo = __uint_as_float(l); hi = __uint_as_float(h);
}

// =====================================================================
// K1: fused embed + gather(perm) + RMSNorm + in_proj GEMM
//     M=65536, K=128, N=512.  Block tile 128x128, micro 8x8, f32x2.
// =====================================================================
#define ATS 132   // As_t stride (floats): %32==4 -> 4-way STS conflict, 16B aligned reads
__global__ __launch_bounds__(256, 2) void k_fused_in(
    const float* __restrict__ feats, const int* __restrict__ coords,
    const float* __restrict__ pos_w, const float* __restrict__ pos_b,
    const float* __restrict__ rms_w, const float* __restrict__ W,
    const int* __restrict__ perm)
{
    extern __shared__ float smem[];
    float* As_t = smem;                 // [128][ATS]  (k-major, transposed)
    float* Bs   = smem + 128*ATS;       // [32][128]
    const int tid  = threadIdx.x;
    const int lane = tid & 31, wrp = tid >> 5;
    const int m0 = blockIdx.x * 128;
    const int nb = blockIdx.y;          // 0..3 (each 128 cols of 512)

    // --- embed + gather + RMSNorm for 128 rows; store transposed ---
    for (int r = wrp; r < 128; r += 8) {
        int m   = m0 + r;
        int src = (m & ~(Lc-1)) + perm[m];
        float c0 = (float)coords[src*3+0];
        float c1 = (float)coords[src*3+1];
        float c2 = (float)coords[src*3+2];
        float v[4]; float ss = 0.f;
        #pragma unroll
        for (int j = 0; j < 4; ++j) {
            int c = lane + 32*j;
            float val = feats[(size_t)src*Dc + c] + c0*pos_w[c] + c1*pos_w[Dc+c]
                        + c2*pos_w[2*Dc+c] + pos_b[c];
            v[j] = val; ss += val*val;
        }
        #pragma unroll
        for (int o = 16; o > 0; o >>= 1) ss += __shfl_xor_sync(0xffffffffu, ss, o);
        float rs = rsqrtf(ss * (1.f/Dc) + EPSc);
        #pragma unroll
        for (int j = 0; j < 4; ++j) {
            int c = lane + 32*j;
            As_t[c*ATS + r] = v[j] * rs * rms_w[c];   // conflict-free (ATS%32==4, c=lane+32j)
        }
    }
    __syncthreads();

    const int ty = tid >> 4, tx = tid & 15;
    const int r0 = ty*8, c0 = tx*8;
    u64 acc[4][8] = {};                 // row-pairs x 8 cols

    for (int kk = 0; kk < 4; ++kk) {
        // load B chunk [32][128]
        #pragma unroll
        for (int i = 0; i < 4; ++i) {
            int idx = tid + i*256;              // 0..1023, each a float4
            int r = idx >> 5, c = (idx & 31) * 4;
            *(float4*)&Bs[r*128 + c] = *(const float4*)&W[(size_t)(kk*32 + r)*512 + nb*128 + c];
        }
        __syncthreads();
        #pragma unroll 4
        for (int k = 0; k < 32; ++k) {
            int kA = kk*32 + k;
            ulonglong2 aA = *(const ulonglong2*)&As_t[kA*ATS + r0];
            ulonglong2 aB = *(const ulonglong2*)&As_t[kA*ATS + r0 + 4];
            u64 a2[4] = {aA.x, aA.y, aB.x, aB.y};
            float4 b0 = *(const float4*)&Bs[k*128 + c0];
            float4 b1 = *(const float4*)&Bs[k*128 + c0 + 4];
            float bf[8] = {b0.x,b0.y,b0.z,b0.w,b1.x,b1.y,b1.z,b1.w};
            #pragma unroll
            for (int c = 0; c < 8; ++c) {
                u64 bb = pk2(bf[c], bf[c]);
                fma2(acc[0][c], a2[0], bb);
                fma2(acc[1][c], a2[1], bb);
                fma2(acc[2][c], a2[2], bb);
                fma2(acc[3][c], a2[3], bb);
            }
        }
        __syncthreads();
    }

    // epilogue: rows r0+2rp (lo) and r0+2rp+1 (hi)
    float* dst = (nb < 2) ? g_xi : g_z;
    int ncol = (nb & 1)*128 + c0;
    #pragma unroll
    for (int rp = 0; rp < 4; ++rp) {
        float lo[8], hi[8];
        #pragma unroll
        for (int c = 0; c < 8; ++c) upk2(acc[rp][c], lo[c], hi[c]);
        size_t ma = (size_t)(m0 + r0 + 2*rp)*DIc + ncol;
        size_t mb = ma + DIc;
        *(float4*)&dst[ma]   = make_float4(lo[0],lo[1],lo[2],lo[3]);
        *(float4*)&dst[ma+4] = make_float4(lo[4],lo[5],lo[6],lo[7]);
        *(float4*)&dst[mb]   = make_float4(hi[0],hi[1],hi[2],hi[3]);
        *(float4*)&dst[mb+4] = make_float4(hi[4],hi[5],hi[6],hi[7]);
    }
}

// =====================================================================
// K2: depthwise causal conv (K=4) + silu
// =====================================================================
__global__ __launch_bounds__(256) void k_conv(
    const float* __restrict__ cw, const float* __restrict__ cb)
{
    int idx = blockIdx.x*256 + threadIdx.x;
    int d = idx & (DIc-1);
    int t = (idx >> 8) & (Lc-1);
    float acc = cb[d];
    #pragma unroll
    for (int j = 0; j < Kc; ++j) {
        int tt = t - (Kc-1) + j;
        if (tt >= 0) acc += g_xi[idx + (j-(Kc-1))*DIc] * cw[d*Kc + j];
    }
    g_xc[idx] = acc / (1.f + __expf(-acc));
}

// =====================================================================
// K3: dbc = xc @ x_proj_w  (M=65536, K=256, N=40 pad 64)
//     Block tile 128x64, micro 8x4, f32x2.
// =====================================================================
__global__ __launch_bounds__(256) void k_xproj(const float* __restrict__ Wg)
{
    __shared__ float As_t[32*ATS];      // chunk transposed [32][ATS]
    __shared__ float Bs[32*64];
    int tid = threadIdx.x;
    int m0 = blockIdx.x*128;
    const int ty = tid >> 4, tx = tid & 15;
    const int r0 = ty*8, c0 = tx*4;
    u64 acc[4][4] = {};

    for (int kk = 0; kk < 256; kk += 32) {
        // A chunk: read g_xc rows, store transposed
        #pragma unroll
        for (int i = 0; i < 16; ++i) {
            int idx = tid + i*256;          // 0..4095
            int c = idx & 31, m = idx >> 5;
            As_t[c*ATS + m] = g_xc[(size_t)(m0+m)*DIc + kk + c];
        }
        // B chunk [32][64] with zero pad
        #pragma unroll
        for (int i = 0; i < 8; ++i) {
            int idx = tid + i*256;          // 0..2047
            int r = idx >> 6, c = idx & 63;
            Bs[r*64 + c] = (c < 40) ? Wg[(size_t)(kk+r)*40 + c] : 0.f;
        }
        __syncthreads();
        #pragma unroll 4
        for (int k = 0; k < 32; ++k) {
            ulonglong2 aA = *(const ulonglong2*)&As_t[k*ATS + r0];
            ulonglong2 aB = *(const ulonglong2*)&As_t[k*ATS + r0 + 4];
            u64 a2[4] = {aA.x, aA.y, aB.x, aB.y};
            float4 b0 = *(const float4*)&Bs[k*64 + c0];
            float bf[4] = {b0.x,b0.y,b0.z,b0.w};
            #pragma unroll
            for (int c = 0; c < 4; ++c) {
                u64 bb = pk2(bf[c], bf[c]);
                fma2(acc[0][c], a2[0], bb);
                fma2(acc[1][c], a2[1], bb);
                fma2(acc[2][c], a2[2], bb);
                fma2(acc[3][c], a2[3], bb);
            }
        }
        __syncthreads();
    }
    #pragma unroll
    for (int rp = 0; rp < 4; ++rp) {
        float lo[4], hi[4];
        #pragma unroll
        for (int c = 0; c < 4; ++c) upk2(acc[rp][c], lo[c], hi[c]);
        int ma = m0 + r0 + 2*rp;
        #pragma unroll
        for (int c = 0; c < 4; ++c) {
            int n = c0 + c;
            if (n < 40) {
                g_dbc[(size_t)ma*40 + n]     = lo[c];
                g_dbc[(size_t)(ma+1)*40 + n] = hi[c];
            }
        }
    }
}

// =====================================================================
// K4: dt = softplus(dt8 @ dt_proj_w + b)  — 32 tokens per block
// =====================================================================
__global__ __launch_bounds__(256) void k_dt(
    const float* __restrict__ dtw, const float* __restrict__ dtb)
{
    __shared__ float ws[8*256];
    __shared__ float dr[32][8];
    int tid = threadIdx.x;
    int m0 = blockIdx.x*32;
    #pragma unroll
    for (int i = 0; i < 8; ++i) ws[tid + i*256] = dtw[tid + i*256];
    { int t = tid >> 3, k = tid & 7; dr[t][k] = g_dbc[(size_t)(m0+t)*40 + k]; }
    __syncthreads();
    float b = dtb[tid];
    float wr[8];
    #pragma unroll
    for (int k = 0; k < 8; ++k) wr[k] = ws[k*256 + tid];
    for (int t = 0; t < 32; ++t) {
        float v = b;
        #pragma unroll
        for (int k = 0; k < 8; ++k) v += dr[t][k]*wr[k];
        float sp = (v > 15.f) ? v : __logf(1.f + __expf(v));
        g_dt[(size_t)(m0+t)*DIc + tid] = sp;
    }
}

// =====================================================================
// K5: scan pass 1 — per-chunk local final state (from zero) + sum(dt)
// =====================================================================
__global__ __launch_bounds__(256) void k_scan1(const float* __restrict__ A_log)
{
    __shared__ float Bsh[Tc][DSc];
    int blk = blockIdx.x;
    int b = blk >> 7, ch = blk & (NCH-1);
    int base = b*Lc + ch*Tc;
    int tid = threadIdx.x;
    for (int i = tid; i < Tc*DSc; i += 256) {
        int t = i >> 4, s = i & 15;
        Bsh[t][s] = g_dbc[(size_t)(base+t)*40 + DTRc + s];
    }
    __syncthreads();
    int d = tid;
    float a0 = -__expf(A_log[d*DSc]);
    bool uni = true;
    #pragma unroll
    for (int s = 1; s < DSc; ++s) {
        float as = -__expf(A_log[d*DSc+s]);
        uni = uni && (fabsf(as - (float)(s+1)*a0) <= 1e-4f*fabsf((float)(s+1)*a0) + 1e-6f);
    }
    float h[DSc];
    #pragma unroll
    for (int s = 0; s < DSc; ++s) h[s] = 0.f;
    float sdt = 0.f;
    if (uni) {
        for (int t = 0; t < Tc; ++t) {
            float dt = g_dt[(size_t)(base+t)*DIc + d];
            float x  = g_xc[(size_t)(base+t)*DIc + d];
            sdt += dt;
            float u = dt*x;
            float e1 = __expf(dt*a0);
            float pk = 1.f;
            #pragma unroll
            for (int s = 0; s < DSc; ++s) { pk *= e1; h[s] = pk*h[s] + u*Bsh[t][s]; }
        }
    } else {
        for (int t = 0; t < Tc; ++t) {
            float dt = g_dt[(size_t)(base+t)*DIc + d];
            float x  = g_xc[(size_t)(base+t)*DIc + d];
            sdt += dt;
            float u = dt*x;
            #pragma unroll
            for (int s = 0; s < DSc; ++s) {
                float as = -__expf(A_log[d*DSc+s]);
                h[s] = __expf(dt*as)*h[s] + u*Bsh[t][s];
            }
        }
    }
    size_t co = ((size_t)blk*DIc + d)*DSc;
    #pragma unroll
    for (int s = 0; s < DSc; ++s) g_ch[co+s] = h[s];
    g_sdt[(size_t)blk*DIc + d] = sdt;
}

// =====================================================================
// K6: sequential chunk combine -> carry-in state per chunk
// =====================================================================
__global__ __launch_bounds__(256) void k_comb(const float* __restrict__ A_log)
{
    int id = blockIdx.x*256 + threadIdx.x;
    int b = id >> 12;
    int d = (id >> 4) & (DIc-1);
    int s = id & 15;
    float a = -__expf(A_log[d*DSc + s]);
    float H = 0.f;
    for (int ch = 0; ch < NCH; ++ch) {
        size_t off = ((size_t)(b*NCH+ch)*DIc + d)*DSc + s;
        g_hin[off] = H;
        float sdt = g_sdt[(size_t)(b*NCH+ch)*DIc + d];
        H = __expf(a*sdt)*H + g_ch[off];
    }
}

// =====================================================================
// K7: scan pass 2 — exact replay with carry-in, fused +xc*D and *silu(z)
// =====================================================================
__global__ __launch_bounds__(256) void k_scan2(
    const float* __restrict__ A_log, const float* __restrict__ Dp)
{
    __shared__ float Bsh[Tc][DSc];
    __shared__ float Csh[Tc][DSc];
    int blk = blockIdx.x;
    int b = blk >> 7, ch = blk & (NCH-1);
    int base = b*Lc + ch*Tc;
    int tid = threadIdx.x;
    for (int i = tid; i < Tc*DSc; i += 256) {
        int t = i >> 4, s = i & 15;
        Bsh[t][s] = g_dbc[(size_t)(base+t)*40 + DTRc + s];
        Csh[t][s] = g_dbc[(size_t)(base+t)*40 + DTRc + DSc + s];
    }
    __syncthreads();
    int d = tid;
    float a0 = -__expf(A_log[d*DSc]);
    bool uni = true;
    #pragma unroll
    for (int s = 1; s < DSc; ++s) {
        float as = -__expf(A_log[d*DSc+s]);
        uni = uni && (fabsf(as - (float)(s+1)*a0) <= 1e-4f*fabsf((float)(s+1)*a0) + 1e-6f);
    }
    float h[DSc];
    size_t ho = ((size_t)blk*DIc + d)*DSc;
    #pragma unroll
    for (int s = 0; s < DSc; ++s) h[s] = g_hin[ho+s];
    float dp = Dp[d];
    if (uni) {
        for (int t = 0; t < Tc; ++t) {
            float dt = g_dt[(size_t)(base+t)*DIc + d];
            float x  = g_xc[(size_t)(base+t)*DIc + d];
            float u = dt*x;
            float e1 = __expf(dt*a0);
            float pk = 1.f, y = 0.f;
            #pragma unroll
            for (int s = 0; s < DSc; ++s) {
                pk *= e1;
                h[s] = pk*h[s] + u*Bsh[t][s];
                y += h[s]*Csh[t][s];
            }
            float zz = g_z[(size_t)(base+t)*DIc + d];
            float sil = zz / (1.f + __expf(-zz));
            g_y[(size_t)(base+t)*DIc + d] = (y + x*dp)*sil;
        }
    } else {
        for (int t = 0; t < Tc; ++t) {
            float dt = g_dt[(size_t)(base+t)*DIc + d];
            float x  = g_xc[(size_t)(base+t)*DIc + d];
            float u = dt*x;
            float y = 0.f;
            #pragma unroll
            for (int s = 0; s < DSc; ++s) {
                float as = -__expf(A_log[d*DSc+s]);
                h[s] = __expf(dt*as)*h[s] + u*Bsh[t][s];
                y += h[s]*Csh[t][s];
            }
            float zz = g_z[(size_t)(base+t)*DIc + d];
            float sil = zz / (1.f + __expf(-zz));
            g_y[(size_t)(base+t)*DIc + d] = (y + x*dp)*sil;
        }
    }
}

// =====================================================================
// K8: out = y @ out_proj_w  (M=65536, K=256, N=128)
//     Block tile 128x128, micro 8x8, f32x2, transposed A chunks.
// =====================================================================
__global__ __launch_bounds__(256, 2) void k_outproj(const float* __restrict__ Wg)
{
    __shared__ float As_t[32*ATS];
    __shared__ float Bs[32*128];
    int tid = threadIdx.x;
    int m0 = blockIdx.x*128;
    const int ty = tid >> 4, tx = tid & 15;
    const int r0 = ty*8, c0 = tx*8;
    u64 acc[4][8] = {};

    for (int kk = 0; kk < 256; kk += 32) {
        #pragma unroll
        for (int i = 0; i < 16; ++i) {
            int idx = tid + i*256;
            int c = idx & 31, m = idx >> 5;
            As_t[c*ATS + m] = g_y[(size_t)(m0+m)*DIc + kk + c];
        }
        #pragma unroll
        for (int i = 0; i < 4; ++i) {
            int idx = tid + i*256;              // float4 over [32][128]
            int r = idx >> 5, c = (idx & 31) * 4;
            *(float4*)&Bs[r*128 + c] = *(const float4*)&Wg[(size_t)(kk + r)*Dc + c];
        }
        __syncthreads();
        #pragma unroll 4
        for (int k = 0; k < 32; ++k) {
            ulonglong2 aA = *(const ulonglong2*)&As_t[k*ATS + r0];
            ulonglong2 aB = *(const ulonglong2*)&As_t[k*ATS + r0 + 4];
            u64 a2[4] = {aA.x, aA.y, aB.x, aB.y};
            float4 b0 = *(const float4*)&Bs[k*128 + c0];
            float4 b1 = *(const float4*)&Bs[k*128 + c0 + 4];
            float bf[8] = {b0.x,b0.y,b0.z,b0.w,b1.x,b1.y,b1.z,b1.w};
            #pragma unroll
            for (int c = 0; c < 8; ++c) {
                u64 bb = pk2(bf[c], bf[c]);
                fma2(acc[0][c], a2[0], bb);
                fma2(acc[1][c], a2[1], bb);
                fma2(acc[2][c], a2[2], bb);
                fma2(acc[3][c], a2[3], bb);
            }
        }
        __syncthreads();
    }
    #pragma unroll
    for (int rp = 0; rp < 4; ++rp) {
        float lo[8], hi[8];
        #pragma unroll
        for (int c = 0; c < 8; ++c) upk2(acc[rp][c], lo[c], hi[c]);
        size_t ma = (size_t)(m0 + r0 + 2*rp)*Dc + c0;
        size_t mb = ma + Dc;
        *(float4*)&g_op[ma]   = make_float4(lo[0],lo[1],lo[2],lo[3]);
        *(float4*)&g_op[ma+4] = make_float4(lo[4],lo[5],lo[6],lo[7]);
        *(float4*)&g_op[mb]   = make_float4(hi[0],hi[1],hi[2],hi[3]);
        *(float4*)&g_op[mb+4] = make_float4(hi[4],hi[5],hi[6],hi[7]);
    }
}

// =====================================================================
// K9: LayerNorm + inverse-permutation scatter (one warp per row)
// =====================================================================
__global__ __launch_bounds__(256) void k_ln(
    const int* __restrict__ perm,
    const float* __restrict__ ln_w, const float* __restrict__ ln_b,
    float* __restrict__ out)
{
    int wrp = threadIdx.x >> 5, lane = threadIdx.x & 31;
    int m = blockIdx.x*8 + wrp;
    float4 v4 = *(const float4*)(g_op + (size_t)m*Dc + lane*4);
    float v[4] = {v4.x, v4.y, v4.z, v4.w};
    float sum = 0.f, ss = 0.f;
    #pragma unroll
    for (int j = 0; j < 4; ++j) { sum += v[j]; ss += v[j]*v[j]; }
    #pragma unroll
    for (int o = 16; o > 0; o >>= 1) {
        sum += __shfl_xor_sync(0xffffffffu, sum, o);
        ss  += __shfl_xor_sync(0xffffffffu, ss, o);
    }
    float mu  = sum * (1.f/Dc);
    float var = ss * (1.f/Dc) - mu*mu;
    float rs  = rsqrtf(var + EPSc);
    int dst = (m & ~(Lc-1)) + perm[m];
    float4 o4;
    int c = lane*4;
    o4.x = (v[0]-mu)*rs*ln_w[c+0] + ln_b[c+0];
    o4.y = (v[1]-mu)*rs*ln_w[c+1] + ln_b[c+1];
    o4.z = (v[2]-mu)*rs*ln_w[c+2] + ln_b[c+2];
    o4.w = (v[3]-mu)*rs*ln_w[c+3] + ln_b[c+3];
    *(float4*)(out + (size_t)dst*Dc + c) = o4;
}

// =====================================================================
extern "C" void kernel_launch(void* const* d_in, const int* in_sizes, int n_in,
                              void* d_out, int out_size)
{
    const float* feats      = (const float*)d_in[0];
    const float* pos_w      = (const float*)d_in[1];
    const float* pos_b      = (const float*)d_in[2];
    const float* rms_w      = (const float*)d_in[3];
    const float* in_proj_w  = (const float*)d_in[4];
    const float* conv_w     = (const float*)d_in[5];
    const float* conv_b     = (const float*)d_in[6];
    const float* x_proj_w   = (const float*)d_in[7];
    const float* dt_proj_w  = (const float*)d_in[8];
    const float* dt_proj_b  = (const float*)d_in[9];
    const float* A_log      = (const float*)d_in[10];
    const float* D_param    = (const float*)d_in[11];
    const float* out_proj_w = (const float*)d_in[12];
    const float* ln_w       = (const float*)d_in[13];
    const float* ln_b       = (const float*)d_in[14];
    const int*   coords     = (const int*)  d_in[15];
    const int*   perm       = (const int*)  d_in[16];
    float* out = (float*)d_out;

    const int smem_in = (128*ATS + 32*128) * 4;   // ~84 KB
    cudaFuncSetAttribute(k_fused_in, cudaFuncAttributeMaxDynamicSharedMemorySize, smem_in);

    k_fused_in<<<dim3(Nc/128, 4), 256, smem_in>>>(feats, coords, pos_w, pos_b,
                                                  rms_w, in_proj_w, perm);
    k_conv   <<<(Nc*DIc)/256, 256>>>(conv_w, conv_b);
    k_xproj  <<<Nc/128, 256>>>(x_proj_w);
    k_dt     <<<Nc/32, 256>>>(dt_proj_w, dt_proj_b);
    k_scan1  <<<Bc*NCH, 256>>>(A_log);
    k_comb   <<<(Bc*DIc*DSc)/256, 256>>>(A_log);
    k_scan2  <<<Bc*NCH, 256>>>(A_log, D_param);
    k_outproj<<<Nc/128, 256>>>(out_proj_w);
    k_ln     <<<Nc/8, 256>>>(perm, ln_w, ln_b, out);
}